// round 14
// baseline (speedup 1.0000x reference)
#include <cuda_runtime.h>
#include <cstdint>
#include <cstddef>
#include <math_constants.h>

#define WIN_ 256
typedef unsigned long long u64;

// ---------------- packed f32x2 helpers ----------------
__device__ __forceinline__ u64 bc2(float x) {
    u64 r; asm("mov.b64 %0, {%1, %1};" : "=l"(r) : "f"(x)); return r;
}
__device__ __forceinline__ void fma2(u64& d, u64 a, u64 b) {
    asm("fma.rn.f32x2 %0, %1, %2, %0;" : "+l"(d) : "l"(a), "l"(b));
}
__device__ __forceinline__ void mul2(u64& d, u64 a) {
    asm("mul.rn.f32x2 %0, %0, %1;" : "+l"(d) : "l"(a));
}
__device__ __forceinline__ float2 up2(u64 v) {
    float2 f; asm("mov.b64 {%0, %1}, %2;" : "=f"(f.x), "=f"(f.y) : "l"(v)); return f;
}

// ---------------- device-global scratch ----------------
__device__ float g_q1[(size_t)2 * 16 * 1024 * 128];
__device__ float g_q2[(size_t)2 * 16 * 1024 * 128];
__device__ float g_k1[(size_t)2 * 8 * 1024 * 128];
__device__ float g_k2[(size_t)2 * 8 * 1024 * 128];
__device__ float g_v [(size_t)2 * 8 * 1024 * 128];
__device__ float g_ao[(size_t)2 * 1024 * 2048];

// ============================================================================
// fp32 SGEMM 64x128 tile, BK=16, 256 threads, double-buffered, FFMA2 core.
// 3 CTAs/SM target (acc=32 regs): 24 warps/SM vs 16 — attack issue starvation.
// Inner k-step: 1 LDS.128(A) + 2 LDS.128(B) + 4 bc2 + 16 FFMA2.
// ============================================================================
template<int MODE>
__global__ __launch_bounds__(256, 3)
void gemm_kernel(const float* __restrict__ A,
                 const float* __restrict__ W0,
                 const float* __restrict__ W1,
                 const float* __restrict__ W2,
                 const float* __restrict__ fc,
                 const float* __restrict__ fs,
                 float* __restrict__ outp)
{
    __shared__ float As[2][16][68];    // [k][m], 64 + 4 pad
    __shared__ float Bs[2][16][128];   // [k][n]

    const int tid = threadIdx.x;
    const int tx  = tid & 15;
    const int ty  = tid >> 4;          // 0..15, rows ty*4..+3
    const int bm  = blockIdx.y * 64;
    const int ct  = blockIdx.x;

    const float* Ap = (MODE == 1) ? g_ao : A;
    const float* Bp;
    int ldb, coff;
    if (MODE == 1)    { Bp = W0; ldb = 2048; coff = ct * 128; }
    else if (ct < 16) { Bp = W0; ldb = 2048; coff = ct * 128; }
    else if (ct < 24) { Bp = W1; ldb = 1024; coff = (ct - 16) * 128; }
    else              { Bp = W2; ldb = 1024; coff = (ct - 24) * 128; }

    const int K  = 2048;
    const int KT = K / 16;

    const int a_row = tid >> 2;        // 0..63
    const int a_k4  = (tid & 3) << 2;
    const int b_k   = tid >> 5;        // 0..7 (+8 for p=1)
    const int b_c4  = (tid & 31) << 2;

    u64 acc[4][4];                     // 4 rows x 8 cols (packed pairs)
#pragma unroll
    for (int i = 0; i < 4; ++i)
#pragma unroll
        for (int j = 0; j < 4; ++j) acc[i][j] = 0ull;

    float4 ra, rb[2];
    ra = *(const float4*)&Ap[(size_t)(bm + a_row) * K + a_k4];
#pragma unroll
    for (int p = 0; p < 2; ++p)
        rb[p] = *(const float4*)&Bp[(size_t)(b_k + p * 8) * ldb + coff + b_c4];

    As[0][a_k4 + 0][a_row] = ra.x;
    As[0][a_k4 + 1][a_row] = ra.y;
    As[0][a_k4 + 2][a_row] = ra.z;
    As[0][a_k4 + 3][a_row] = ra.w;
#pragma unroll
    for (int p = 0; p < 2; ++p)
        *(float4*)&Bs[0][b_k + p * 8][b_c4] = rb[p];
    __syncthreads();

    for (int kt = 0; kt < KT; ++kt) {
        const int buf = kt & 1;
        if (kt + 1 < KT) {
            const int ko = (kt + 1) * 16;
            ra = *(const float4*)&Ap[(size_t)(bm + a_row) * K + ko + a_k4];
#pragma unroll
            for (int p = 0; p < 2; ++p)
                rb[p] = *(const float4*)&Bp[(size_t)(ko + b_k + p * 8) * ldb + coff + b_c4];
        }
#pragma unroll
        for (int k = 0; k < 16; ++k) {
            float4 a0 = *(const float4*)&As[buf][k][ty * 4];
            ulonglong2 b0 = *(const ulonglong2*)&Bs[buf][k][tx * 4];
            ulonglong2 b1 = *(const ulonglong2*)&Bs[buf][k][64 + tx * 4];
            u64 bv[4] = {b0.x, b0.y, b1.x, b1.y};
            float av[4] = {a0.x, a0.y, a0.z, a0.w};
#pragma unroll
            for (int i = 0; i < 4; ++i) {
                u64 ai = bc2(av[i]);
#pragma unroll
                for (int j = 0; j < 4; ++j)
                    fma2(acc[i][j], ai, bv[j]);
            }
        }
        if (kt + 1 < KT) {
            const int nb = buf ^ 1;
            As[nb][a_k4 + 0][a_row] = ra.x;
            As[nb][a_k4 + 1][a_row] = ra.y;
            As[nb][a_k4 + 2][a_row] = ra.z;
            As[nb][a_k4 + 3][a_row] = ra.w;
#pragma unroll
            for (int p = 0; p < 2; ++p)
                *(float4*)&Bs[nb][b_k + p * 8][b_c4] = rb[p];
        }
        __syncthreads();
    }

    if (MODE == 0) {
#pragma unroll
        for (int i = 0; i < 4; ++i) {
            const int row = bm + ty * 4 + i;
            const int bb  = row >> 10;
            const int ss  = row & 1023;
#pragma unroll
            for (int j2 = 0; j2 < 4; ++j2) {
                const int nl = (j2 < 2) ? (tx * 4 + 2 * j2) : (64 + tx * 4 + 2 * j2 - 4);
                const int t  = nl >> 1;
                float2 xz = up2(acc[i][j2]);
                const float xr = xz.x;
                const float xi = xz.y;
                if (ct < 16) {
                    const int h = ct;
                    const size_t off = ((size_t)(bb * 16 + h) * 1024 + ss) * 128 + nl;
                    const float c1 = fc[ss * 64 + t], s1 = fs[ss * 64 + t];
                    g_q1[off]     = xr * c1 - xi * s1;
                    g_q1[off + 1] = xr * s1 + xi * c1;
                    const float cw = fc[WIN_ * 64 + t], sw = fs[WIN_ * 64 + t];
                    g_q2[off]     = xr * cw - xi * sw;
                    g_q2[off + 1] = xr * sw + xi * cw;
                } else if (ct < 24) {
                    const int h = ct - 16;
                    const size_t off = ((size_t)(bb * 8 + h) * 1024 + ss) * 128 + nl;
                    const float c1 = fc[ss * 64 + t], s1 = fs[ss * 64 + t];
                    g_k1[off]     = xr * c1 - xi * s1;
                    g_k1[off + 1] = xr * s1 + xi * c1;
                    g_k2[off]     = xr;
                    g_k2[off + 1] = xi;
                } else {
                    const int h = ct - 24;
                    const size_t off = ((size_t)(bb * 8 + h) * 1024 + ss) * 128 + nl;
                    g_v[off]     = xr;
                    g_v[off + 1] = xi;
                }
            }
        }
    } else {
#pragma unroll
        for (int i = 0; i < 4; ++i) {
            const size_t row = (size_t)(bm + ty * 4 + i);
            float2 p0 = up2(acc[i][0]), p1 = up2(acc[i][1]);
            float2 p2 = up2(acc[i][2]), p3 = up2(acc[i][3]);
            *(float4*)&outp[row * 2048 + ct * 128 + tx * 4] =
                make_float4(p0.x, p0.y, p1.x, p1.y);
            *(float4*)&outp[row * 2048 + ct * 128 + 64 + tx * 4] =
                make_float4(p2.x, p2.y, p3.x, p3.y);
        }
    }
}

// ============================================================================
// Flash attention — byte-identical to R13 best (barrier-reduced, K/V dbuf).
// ============================================================================
__device__ __forceinline__ void load_T64(float* __restrict__ dst,
                                         const float* __restrict__ src)
{
    const int t  = threadIdx.x;
    const int r  = t >> 2;
    const int d0 = (t & 3) * 32;
    const float* s = src + (size_t)r * 128 + d0;
#pragma unroll
    for (int q = 0; q < 8; ++q) {
        float4 v = *(const float4*)(s + q * 4);
        const int d = d0 + q * 4;
        dst[(d + 0) * 64 + r] = v.x;
        dst[(d + 1) * 64 + r] = v.y;
        dst[(d + 2) * 64 + r] = v.z;
        dst[(d + 3) * 64 + r] = v.w;
    }
}

__device__ __forceinline__ void qk_gemm(const float* __restrict__ Qs,
                                        const float* __restrict__ Ks,
                                        int ty, int tx, u64 Sp[4][2])
{
#pragma unroll
    for (int i = 0; i < 4; ++i) { Sp[i][0] = 0ull; Sp[i][1] = 0ull; }
#pragma unroll 4
    for (int d = 0; d < 128; ++d) {
        float4 a = *(const float4*)&Qs[d * 64 + ty * 4];
        ulonglong2 b = *(const ulonglong2*)&Ks[d * 64 + tx * 4];
        float av[4] = {a.x, a.y, a.z, a.w};
#pragma unroll
        for (int i = 0; i < 4; ++i) {
            u64 ai = bc2(av[i]);
            fma2(Sp[i][0], ai, b.x);
            fma2(Sp[i][1], ai, b.y);
        }
    }
}

__global__ __launch_bounds__(256, 1)
void flash_kernel()
{
    extern __shared__ float smf[];
    float* Qa  = smf;
    float* Qb  = smf + 8192;
    float* Ksb = smf + 16384;
    float* Vsb = smf + 32768;
    float* Ps  = smf + 49152;

    const int bh = blockIdx.y;
    const int b  = bh >> 4;
    const int h  = bh & 15;
    const int kh = h >> 1;
    const int qt = 15 - (int)blockIdx.x;
    const int i0 = qt * 64;

    const int tid = threadIdx.x;
    const int ty  = tid >> 4;
    const int tx  = tid & 15;
    const float scale = 0.08838834764831845f;

    const int lr  = tid >> 2;
    const int ld0 = (tid & 3) * 32;

    const float* kb1 = g_k1 + ((size_t)(b * 8 + kh) * 1024) * 128;
    const float* kb2 = g_k2 + ((size_t)(b * 8 + kh) * 1024) * 128;
    const float* vb  = g_v  + ((size_t)(b * 8 + kh) * 1024) * 128;

    float4 kreg[8], vreg[8];

#define ZONE_OF(j0) (((j0) >= i0 - 192) ? 0 : (((j0) == i0 - 256) ? 1 : 2))
#define PREFETCH(ktv) do { \
    const int j0p = (ktv) * 64; \
    const float* kb = ((ZONE_OF(j0p) == 2) ? kb2 : kb1) + (size_t)j0p * 128; \
    const float* vp = vb + (size_t)j0p * 128; \
    const float* ks = kb + (size_t)lr * 128 + ld0; \
    const float* vs = vp + (size_t)lr * 128 + ld0; \
    _Pragma("unroll") \
    for (int q = 0; q < 8; ++q) { \
        kreg[q] = *(const float4*)(ks + q * 4); \
        vreg[q] = *(const float4*)(vs + q * 4); \
    } } while (0)

    PREFETCH(0);
    load_T64(Qa, g_q1 + ((size_t)(b * 16 + h) * 1024 + i0) * 128);
    load_T64(Qb, g_q2 + ((size_t)(b * 16 + h) * 1024 + i0) * 128);

    u64 Op[4][4];
    float mo[4], l[4];
#pragma unroll
    for (int i = 0; i < 4; ++i) {
        mo[i] = -CUDART_INF_F;
        l[i]  = 0.f;
#pragma unroll
        for (int c = 0; c < 4; ++c) Op[i][c] = 0ull;
    }

    for (int kt = 0; kt <= qt; ++kt) {
        const int j0   = kt * 64;
        const int zone = ZONE_OF(j0);
        const int buf  = kt & 1;
        float* Ks = Ksb + buf * 8192;
        float* Vs = Vsb + buf * 8192;

#pragma unroll
        for (int q = 0; q < 8; ++q) {
            const int d = ld0 + q * 4;
            Ks[(d + 0) * 64 + lr] = kreg[q].x;
            Ks[(d + 1) * 64 + lr] = kreg[q].y;
            Ks[(d + 2) * 64 + lr] = kreg[q].z;
            Ks[(d + 3) * 64 + lr] = kreg[q].w;
            *(float4*)&Vs[lr * 128 + d] = vreg[q];
        }
        if (kt < qt) PREFETCH(kt + 1);
        __syncthreads();

        u64 SpA[4][2];
        qk_gemm((zone == 2) ? Qb : Qa, Ks, ty, tx, SpA);

        float val[4][4];
        if (zone == 1) {
            float* Kalt = Ksb + (buf ^ 1) * 8192;
            __syncthreads();
            load_T64(Kalt, kb2 + (size_t)j0 * 128);
            __syncthreads();
            u64 SpB[4][2];
            qk_gemm(Qb, Kalt, ty, tx, SpB);
            __syncthreads();
#pragma unroll
            for (int i = 0; i < 4; ++i) {
                const int ig = i0 + ty * 4 + i;
                float2 a0 = up2(SpA[i][0]), a1 = up2(SpA[i][1]);
                float2 b0 = up2(SpB[i][0]), b1 = up2(SpB[i][1]);
                float sa[4]  = {a0.x, a0.y, a1.x, a1.y};
                float sbv[4] = {b0.x, b0.y, b1.x, b1.y};
#pragma unroll
                for (int j = 0; j < 4; ++j) {
                    const int jg = j0 + tx * 4 + j;
                    val[i][j] = ((jg > ig - WIN_) ? sa[j] : sbv[j]) * scale;
                }
            }
        } else {
            const bool diag = (j0 == i0);
#pragma unroll
            for (int i = 0; i < 4; ++i) {
                const int ig = i0 + ty * 4 + i;
                float2 a0 = up2(SpA[i][0]), a1 = up2(SpA[i][1]);
                float sa[4] = {a0.x, a0.y, a1.x, a1.y};
#pragma unroll
                for (int j = 0; j < 4; ++j) {
                    const int jg = j0 + tx * 4 + j;
                    float v = sa[j] * scale;
                    if (diag && jg > ig) v = -CUDART_INF_F;
                    val[i][j] = v;
                }
            }
        }

        float mr[4], al[4];
#pragma unroll
        for (int i = 0; i < 4; ++i) {
            float m = val[i][0];
            m = fmaxf(m, val[i][1]);
            m = fmaxf(m, val[i][2]);
            m = fmaxf(m, val[i][3]);
#pragma unroll
            for (int off = 8; off >= 1; off >>= 1)
                m = fmaxf(m, __shfl_xor_sync(0xffffffffu, m, off));
            m = fmaxf(m, mo[i]);
            al[i] = __expf(mo[i] - m);
            mo[i] = m;
            float s = 0.f;
#pragma unroll
            for (int j = 0; j < 4; ++j) {
                float p = __expf(val[i][j] - m);
                val[i][j] = p;
                s += p;
            }
            mr[i] = s;
        }
#pragma unroll
        for (int i = 0; i < 4; ++i) {
            float s = mr[i];
#pragma unroll
            for (int off = 8; off >= 1; off >>= 1)
                s += __shfl_xor_sync(0xffffffffu, s, off);
            l[i] = l[i] * al[i] + s;
            u64 av = bc2(al[i]);
#pragma unroll
            for (int c = 0; c < 4; ++c) mul2(Op[i][c], av);
            *(float4*)&Ps[(ty * 4 + i) * 64 + tx * 4] =
                make_float4(val[i][0], val[i][1], val[i][2], val[i][3]);
        }
        __syncwarp();

#pragma unroll 2
        for (int j = 0; j < 64; ++j) {
            ulonglong2 v0 = *(const ulonglong2*)&Vs[j * 128 + tx * 4];
            ulonglong2 v1 = *(const ulonglong2*)&Vs[j * 128 + 64 + tx * 4];
            u64 vv[4] = {v0.x, v0.y, v1.x, v1.y};
#pragma unroll
            for (int i = 0; i < 4; ++i) {
                u64 pi = bc2(Ps[(ty * 4 + i) * 64 + j]);
#pragma unroll
                for (int c = 0; c < 4; ++c)
                    fma2(Op[i][c], pi, vv[c]);
            }
        }
    }

#pragma unroll
    for (int i = 0; i < 4; ++i) {
        const float inv = 1.f / l[i];
        u64 iv = bc2(inv);
#pragma unroll
        for (int c = 0; c < 4; ++c) mul2(Op[i][c], iv);
        const int ig = i0 + ty * 4 + i;
        float* dst = g_ao + ((size_t)(b * 1024 + ig)) * 2048 + h * 128;
        float2 p0 = up2(Op[i][0]), p1 = up2(Op[i][1]);
        float2 p2 = up2(Op[i][2]), p3 = up2(Op[i][3]);
        *(float4*)&dst[tx * 4]      = make_float4(p0.x, p0.y, p1.x, p1.y);
        *(float4*)&dst[64 + tx * 4] = make_float4(p2.x, p2.y, p3.x, p3.y);
    }
#undef PREFETCH
#undef ZONE_OF
}

// ============================================================================
extern "C" void kernel_launch(void* const* d_in, const int* in_sizes, int n_in,
                              void* d_out, int out_size)
{
    const float* x  = (const float*)d_in[0];
    const float* fc = (const float*)d_in[1];
    const float* fs = (const float*)d_in[2];
    const float* wq = (const float*)d_in[3];
    const float* wk = (const float*)d_in[4];
    const float* wv = (const float*)d_in[5];
    const float* wo = (const float*)d_in[6];
    float* out = (float*)d_out;

    cudaFuncSetAttribute(flash_kernel,
                         cudaFuncAttributeMaxDynamicSharedMemorySize, 212992);

    gemm_kernel<0><<<dim3(32, 32), 256>>>(x, wq, wk, wv, fc, fs, nullptr);
    flash_kernel<<<dim3(16, 32), 256, 212992>>>();
    gemm_kernel<1><<<dim3(16, 32), 256>>>(nullptr, wo, nullptr, nullptr,
                                          nullptr, nullptr, out);
}

// round 15
// speedup vs baseline: 1.0889x; 1.0889x over previous
#include <cuda_runtime.h>
#include <cstdint>
#include <cstddef>
#include <math_constants.h>

#define WIN_ 256
typedef unsigned long long u64;

// ---------------- packed f32x2 helpers ----------------
__device__ __forceinline__ u64 bc2(float x) {
    u64 r; asm("mov.b64 %0, {%1, %1};" : "=l"(r) : "f"(x)); return r;
}
__device__ __forceinline__ void fma2(u64& d, u64 a, u64 b) {
    asm("fma.rn.f32x2 %0, %1, %2, %0;" : "+l"(d) : "l"(a), "l"(b));
}
__device__ __forceinline__ void mul2(u64& d, u64 a) {
    asm("mul.rn.f32x2 %0, %0, %1;" : "+l"(d) : "l"(a));
}
__device__ __forceinline__ float2 up2(u64 v) {
    float2 f; asm("mov.b64 {%0, %1}, %2;" : "=f"(f.x), "=f"(f.y) : "l"(v)); return f;
}

// ---------------- device-global scratch ----------------
__device__ float g_q1[(size_t)2 * 16 * 1024 * 128];
__device__ float g_q2[(size_t)2 * 16 * 1024 * 128];
__device__ float g_k1[(size_t)2 * 8 * 1024 * 128];
__device__ float g_k2[(size_t)2 * 8 * 1024 * 128];
__device__ float g_v [(size_t)2 * 8 * 1024 * 128];
__device__ float g_ao[(size_t)2 * 1024 * 2048];

// ============================================================================
// fp32 SGEMM 128x128 tile, BK=16, 256 threads, double-buffered, FFMA2 core.
// (Proven R3/R8 kernel, byte-identical — 699us control. LOCKED.)
// ============================================================================
template<int MODE>
__global__ __launch_bounds__(256, 2)
void gemm_kernel(const float* __restrict__ A,
                 const float* __restrict__ W0,
                 const float* __restrict__ W1,
                 const float* __restrict__ W2,
                 const float* __restrict__ fc,
                 const float* __restrict__ fs,
                 float* __restrict__ outp)
{
    __shared__ float As[2][16][132];
    __shared__ float Bs[2][16][128];

    const int tid = threadIdx.x;
    const int tx  = tid & 15;
    const int ty  = tid >> 4;
    const int bm  = blockIdx.y * 128;
    const int ct  = blockIdx.x;

    const float* Ap = (MODE == 1) ? g_ao : A;
    const float* Bp;
    int ldb, coff;
    if (MODE == 1)    { Bp = W0; ldb = 2048; coff = ct * 128; }
    else if (ct < 16) { Bp = W0; ldb = 2048; coff = ct * 128; }
    else if (ct < 24) { Bp = W1; ldb = 1024; coff = (ct - 16) * 128; }
    else              { Bp = W2; ldb = 1024; coff = (ct - 24) * 128; }

    const int K  = 2048;
    const int KT = K / 16;

    const int a_row = tid >> 2;
    const int a_k4  = (tid & 3) << 2;
    const int b_k   = tid >> 5;
    const int b_c4  = (tid & 31) << 2;

    u64 acc[8][4];
#pragma unroll
    for (int i = 0; i < 8; ++i)
#pragma unroll
        for (int j = 0; j < 4; ++j) acc[i][j] = 0ull;

    float4 ra[2], rb[2];
#pragma unroll
    for (int p = 0; p < 2; ++p) {
        ra[p] = *(const float4*)&Ap[(size_t)(bm + a_row + p * 64) * K + a_k4];
        rb[p] = *(const float4*)&Bp[(size_t)(b_k + p * 8) * ldb + coff + b_c4];
    }
#pragma unroll
    for (int p = 0; p < 2; ++p) {
        As[0][a_k4 + 0][a_row + p * 64] = ra[p].x;
        As[0][a_k4 + 1][a_row + p * 64] = ra[p].y;
        As[0][a_k4 + 2][a_row + p * 64] = ra[p].z;
        As[0][a_k4 + 3][a_row + p * 64] = ra[p].w;
        *(float4*)&Bs[0][b_k + p * 8][b_c4] = rb[p];
    }
    __syncthreads();

    for (int kt = 0; kt < KT; ++kt) {
        const int buf = kt & 1;
        if (kt + 1 < KT) {
            const int ko = (kt + 1) * 16;
#pragma unroll
            for (int p = 0; p < 2; ++p) {
                ra[p] = *(const float4*)&Ap[(size_t)(bm + a_row + p * 64) * K + ko + a_k4];
                rb[p] = *(const float4*)&Bp[(size_t)(ko + b_k + p * 8) * ldb + coff + b_c4];
            }
        }
#pragma unroll
        for (int k = 0; k < 16; ++k) {
            float4 a0 = *(const float4*)&As[buf][k][ty * 4];
            float4 a1 = *(const float4*)&As[buf][k][64 + ty * 4];
            ulonglong2 b0 = *(const ulonglong2*)&Bs[buf][k][tx * 4];
            ulonglong2 b1 = *(const ulonglong2*)&Bs[buf][k][64 + tx * 4];
            u64 bv[4] = {b0.x, b0.y, b1.x, b1.y};
            float av[8] = {a0.x, a0.y, a0.z, a0.w, a1.x, a1.y, a1.z, a1.w};
#pragma unroll
            for (int i = 0; i < 8; ++i) {
                u64 ai = bc2(av[i]);
#pragma unroll
                for (int j = 0; j < 4; ++j)
                    fma2(acc[i][j], ai, bv[j]);
            }
        }
        if (kt + 1 < KT) {
            const int nb = buf ^ 1;
#pragma unroll
            for (int p = 0; p < 2; ++p) {
                As[nb][a_k4 + 0][a_row + p * 64] = ra[p].x;
                As[nb][a_k4 + 1][a_row + p * 64] = ra[p].y;
                As[nb][a_k4 + 2][a_row + p * 64] = ra[p].z;
                As[nb][a_k4 + 3][a_row + p * 64] = ra[p].w;
                *(float4*)&Bs[nb][b_k + p * 8][b_c4] = rb[p];
            }
        }
        __syncthreads();
    }

    if (MODE == 0) {
#pragma unroll
        for (int i = 0; i < 8; ++i) {
            const int ml  = (i < 4) ? (ty * 4 + i) : (64 + ty * 4 + i - 4);
            const int row = bm + ml;
            const int bb  = row >> 10;
            const int ss  = row & 1023;
#pragma unroll
            for (int j2 = 0; j2 < 4; ++j2) {
                const int nl = (j2 < 2) ? (tx * 4 + 2 * j2) : (64 + tx * 4 + 2 * j2 - 4);
                const int t  = nl >> 1;
                float2 xz = up2(acc[i][j2]);
                const float xr = xz.x;
                const float xi = xz.y;
                if (ct < 16) {
                    const int h = ct;
                    const size_t off = ((size_t)(bb * 16 + h) * 1024 + ss) * 128 + nl;
                    const float c1 = fc[ss * 64 + t], s1 = fs[ss * 64 + t];
                    g_q1[off]     = xr * c1 - xi * s1;
                    g_q1[off + 1] = xr * s1 + xi * c1;
                    const float cw = fc[WIN_ * 64 + t], sw = fs[WIN_ * 64 + t];
                    g_q2[off]     = xr * cw - xi * sw;
                    g_q2[off + 1] = xr * sw + xi * cw;
                } else if (ct < 24) {
                    const int h = ct - 16;
                    const size_t off = ((size_t)(bb * 8 + h) * 1024 + ss) * 128 + nl;
                    const float c1 = fc[ss * 64 + t], s1 = fs[ss * 64 + t];
                    g_k1[off]     = xr * c1 - xi * s1;
                    g_k1[off + 1] = xr * s1 + xi * c1;
                    g_k2[off]     = xr;
                    g_k2[off + 1] = xi;
                } else {
                    const int h = ct - 24;
                    const size_t off = ((size_t)(bb * 8 + h) * 1024 + ss) * 128 + nl;
                    g_v[off]     = xr;
                    g_v[off + 1] = xi;
                }
            }
        }
    } else {
#pragma unroll
        for (int i = 0; i < 8; ++i) {
            const int ml = (i < 4) ? (ty * 4 + i) : (64 + ty * 4 + i - 4);
            const size_t row = (size_t)(bm + ml);
            float2 p0 = up2(acc[i][0]), p1 = up2(acc[i][1]);
            float2 p2 = up2(acc[i][2]), p3 = up2(acc[i][3]);
            *(float4*)&outp[row * 2048 + ct * 128 + tx * 4] =
                make_float4(p0.x, p0.y, p1.x, p1.y);
            *(float4*)&outp[row * 2048 + ct * 128 + 64 + tx * 4] =
                make_float4(p2.x, p2.y, p3.x, p3.y);
        }
    }
}

// ============================================================================
// Flash attention v6: R13 structure (K/V dbuf, 1 block sync/tile, prefetch)
// + qk software pipeline (hide LDS latency) + PV float4-Ps loads.
// ============================================================================
__device__ __forceinline__ void load_T64(float* __restrict__ dst,
                                         const float* __restrict__ src)
{
    const int t  = threadIdx.x;
    const int r  = t >> 2;
    const int d0 = (t & 3) * 32;
    const float* s = src + (size_t)r * 128 + d0;
#pragma unroll
    for (int q = 0; q < 8; ++q) {
        float4 v = *(const float4*)(s + q * 4);
        const int d = d0 + q * 4;
        dst[(d + 0) * 64 + r] = v.x;
        dst[(d + 1) * 64 + r] = v.y;
        dst[(d + 2) * 64 + r] = v.z;
        dst[(d + 3) * 64 + r] = v.w;
    }
}

// 2-stage software-pipelined QK: preload d+1 before computing d.
__device__ __forceinline__ void qk_gemm(const float* __restrict__ Qs,
                                        const float* __restrict__ Ks,
                                        int ty, int tx, u64 Sp[4][2])
{
#pragma unroll
    for (int i = 0; i < 4; ++i) { Sp[i][0] = 0ull; Sp[i][1] = 0ull; }

    float4     ac = *(const float4*)&Qs[ty * 4];
    ulonglong2 bc = *(const ulonglong2*)&Ks[tx * 4];
#pragma unroll 4
    for (int d = 0; d < 128; ++d) {
        float4     an;
        ulonglong2 bn;
        if (d < 127) {
            an = *(const float4*)&Qs[(d + 1) * 64 + ty * 4];
            bn = *(const ulonglong2*)&Ks[(d + 1) * 64 + tx * 4];
        }
        float av[4] = {ac.x, ac.y, ac.z, ac.w};
#pragma unroll
        for (int i = 0; i < 4; ++i) {
            u64 ai = bc2(av[i]);
            fma2(Sp[i][0], ai, bc.x);
            fma2(Sp[i][1], ai, bc.y);
        }
        ac = an;
        bc = bn;
    }
}

__global__ __launch_bounds__(256, 1)
void flash_kernel()
{
    extern __shared__ float smf[];
    float* Qa  = smf;                 //  8192
    float* Qb  = smf + 8192;          //  8192
    float* Ksb = smf + 16384;         //  2 x 8192
    float* Vsb = smf + 32768;         //  2 x 8192
    float* Ps  = smf + 49152;         //  4096

    const int bh = blockIdx.y;
    const int b  = bh >> 4;
    const int h  = bh & 15;
    const int kh = h >> 1;
    const int qt = 15 - (int)blockIdx.x;
    const int i0 = qt * 64;

    const int tid = threadIdx.x;
    const int ty  = tid >> 4;
    const int tx  = tid & 15;
    const float scale = 0.08838834764831845f;

    const int lr  = tid >> 2;
    const int ld0 = (tid & 3) * 32;

    const float* kb1 = g_k1 + ((size_t)(b * 8 + kh) * 1024) * 128;
    const float* kb2 = g_k2 + ((size_t)(b * 8 + kh) * 1024) * 128;
    const float* vb  = g_v  + ((size_t)(b * 8 + kh) * 1024) * 128;

    float4 kreg[8], vreg[8];

#define ZONE_OF(j0) (((j0) >= i0 - 192) ? 0 : (((j0) == i0 - 256) ? 1 : 2))
#define PREFETCH(ktv) do { \
    const int j0p = (ktv) * 64; \
    const float* kb = ((ZONE_OF(j0p) == 2) ? kb2 : kb1) + (size_t)j0p * 128; \
    const float* vp = vb + (size_t)j0p * 128; \
    const float* ks = kb + (size_t)lr * 128 + ld0; \
    const float* vs = vp + (size_t)lr * 128 + ld0; \
    _Pragma("unroll") \
    for (int q = 0; q < 8; ++q) { \
        kreg[q] = *(const float4*)(ks + q * 4); \
        vreg[q] = *(const float4*)(vs + q * 4); \
    } } while (0)

    PREFETCH(0);
    load_T64(Qa, g_q1 + ((size_t)(b * 16 + h) * 1024 + i0) * 128);
    load_T64(Qb, g_q2 + ((size_t)(b * 16 + h) * 1024 + i0) * 128);

    u64 Op[4][4];
    float mo[4], l[4];
#pragma unroll
    for (int i = 0; i < 4; ++i) {
        mo[i] = -CUDART_INF_F;
        l[i]  = 0.f;
#pragma unroll
        for (int c = 0; c < 4; ++c) Op[i][c] = 0ull;
    }

    for (int kt = 0; kt <= qt; ++kt) {
        const int j0   = kt * 64;
        const int zone = ZONE_OF(j0);
        const int buf  = kt & 1;
        float* Ks = Ksb + buf * 8192;
        float* Vs = Vsb + buf * 8192;

#pragma unroll
        for (int q = 0; q < 8; ++q) {
            const int d = ld0 + q * 4;
            Ks[(d + 0) * 64 + lr] = kreg[q].x;
            Ks[(d + 1) * 64 + lr] = kreg[q].y;
            Ks[(d + 2) * 64 + lr] = kreg[q].z;
            Ks[(d + 3) * 64 + lr] = kreg[q].w;
            *(float4*)&Vs[lr * 128 + d] = vreg[q];
        }
        if (kt < qt) PREFETCH(kt + 1);
        __syncthreads();                 // the ONE block sync per tile

        u64 SpA[4][2];
        qk_gemm((zone == 2) ? Qb : Qa, Ks, ty, tx, SpA);

        float val[4][4];
        if (zone == 1) {
            float* Kalt = Ksb + (buf ^ 1) * 8192;
            __syncthreads();
            load_T64(Kalt, kb2 + (size_t)j0 * 128);
            __syncthreads();
            u64 SpB[4][2];
            qk_gemm(Qb, Kalt, ty, tx, SpB);
            __syncthreads();             // close race with kt+1's STS into buf^1
#pragma unroll
            for (int i = 0; i < 4; ++i) {
                const int ig = i0 + ty * 4 + i;
                float2 a0 = up2(SpA[i][0]), a1 = up2(SpA[i][1]);
                float2 b0 = up2(SpB[i][0]), b1 = up2(SpB[i][1]);
                float sa[4]  = {a0.x, a0.y, a1.x, a1.y};
                float sbv[4] = {b0.x, b0.y, b1.x, b1.y};
#pragma unroll
                for (int j = 0; j < 4; ++j) {
                    const int jg = j0 + tx * 4 + j;
                    val[i][j] = ((jg > ig - WIN_) ? sa[j] : sbv[j]) * scale;
                }
            }
        } else {
            const bool diag = (j0 == i0);
#pragma unroll
            for (int i = 0; i < 4; ++i) {
                const int ig = i0 + ty * 4 + i;
                float2 a0 = up2(SpA[i][0]), a1 = up2(SpA[i][1]);
                float sa[4] = {a0.x, a0.y, a1.x, a1.y};
#pragma unroll
                for (int j = 0; j < 4; ++j) {
                    const int jg = j0 + tx * 4 + j;
                    float v = sa[j] * scale;
                    if (diag && jg > ig) v = -CUDART_INF_F;
                    val[i][j] = v;
                }
            }
        }

        // --- online softmax (identical math) ---
        float mr[4], al[4];
#pragma unroll
        for (int i = 0; i < 4; ++i) {
            float m = val[i][0];
            m = fmaxf(m, val[i][1]);
            m = fmaxf(m, val[i][2]);
            m = fmaxf(m, val[i][3]);
#pragma unroll
            for (int off = 8; off >= 1; off >>= 1)
                m = fmaxf(m, __shfl_xor_sync(0xffffffffu, m, off));
            m = fmaxf(m, mo[i]);
            al[i] = __expf(mo[i] - m);
            mo[i] = m;
            float s = 0.f;
#pragma unroll
            for (int j = 0; j < 4; ++j) {
                float p = __expf(val[i][j] - m);
                val[i][j] = p;
                s += p;
            }
            mr[i] = s;
        }
#pragma unroll
        for (int i = 0; i < 4; ++i) {
            float s = mr[i];
#pragma unroll
            for (int off = 8; off >= 1; off >>= 1)
                s += __shfl_xor_sync(0xffffffffu, s, off);
            l[i] = l[i] * al[i] + s;
            u64 av = bc2(al[i]);
#pragma unroll
            for (int c = 0; c < 4; ++c) mul2(Op[i][c], av);
            *(float4*)&Ps[(ty * 4 + i) * 64 + tx * 4] =
                make_float4(val[i][0], val[i][1], val[i][2], val[i][3]);
        }
        __syncwarp();   // Ps producer == consumer warp

        // --- P @ V: Ps loaded as float4 per 4-j block ---
#pragma unroll 2
        for (int j4 = 0; j4 < 64; j4 += 4) {
            float4 pr[4];
#pragma unroll
            for (int i = 0; i < 4; ++i)
                pr[i] = *(const float4*)&Ps[(ty * 4 + i) * 64 + j4];
            float pa[4][4] = {
                {pr[0].x, pr[0].y, pr[0].z, pr[0].w},
                {pr[1].x, pr[1].y, pr[1].z, pr[1].w},
                {pr[2].x, pr[2].y, pr[2].z, pr[2].w},
                {pr[3].x, pr[3].y, pr[3].z, pr[3].w}};
#pragma unroll
            for (int jj = 0; jj < 4; ++jj) {
                const int j = j4 + jj;
                ulonglong2 v0 = *(const ulonglong2*)&Vs[j * 128 + tx * 4];
                ulonglong2 v1 = *(const ulonglong2*)&Vs[j * 128 + 64 + tx * 4];
                u64 vv[4] = {v0.x, v0.y, v1.x, v1.y};
#pragma unroll
                for (int i = 0; i < 4; ++i) {
                    u64 pi = bc2(pa[i][jj]);
#pragma unroll
                    for (int c = 0; c < 4; ++c)
                        fma2(Op[i][c], pi, vv[c]);
                }
            }
        }
        // no tail sync (K/V double-buffered; WAR closed by the block sync)
    }

    // epilogue
#pragma unroll
    for (int i = 0; i < 4; ++i) {
        const float inv = 1.f / l[i];
        u64 iv = bc2(inv);
#pragma unroll
        for (int c = 0; c < 4; ++c) mul2(Op[i][c], iv);
        const int ig = i0 + ty * 4 + i;
        float* dst = g_ao + ((size_t)(b * 1024 + ig)) * 2048 + h * 128;
        float2 p0 = up2(Op[i][0]), p1 = up2(Op[i][1]);
        float2 p2 = up2(Op[i][2]), p3 = up2(Op[i][3]);
        *(float4*)&dst[tx * 4]      = make_float4(p0.x, p0.y, p1.x, p1.y);
        *(float4*)&dst[64 + tx * 4] = make_float4(p2.x, p2.y, p3.x, p3.y);
    }
#undef PREFETCH
#undef ZONE_OF
}

// ============================================================================
extern "C" void kernel_launch(void* const* d_in, const int* in_sizes, int n_in,
                              void* d_out, int out_size)
{
    const float* x  = (const float*)d_in[0];
    const float* fc = (const float*)d_in[1];
    const float* fs = (const float*)d_in[2];
    const float* wq = (const float*)d_in[3];
    const float* wk = (const float*)d_in[4];
    const float* wv = (const float*)d_in[5];
    const float* wo = (const float*)d_in[6];
    float* out = (float*)d_out;

    cudaFuncSetAttribute(flash_kernel,
                         cudaFuncAttributeMaxDynamicSharedMemorySize, 212992);

    gemm_kernel<0><<<dim3(32, 16), 256>>>(x, wq, wk, wv, fc, fs, nullptr);
    flash_kernel<<<dim3(16, 32), 256, 212992>>>();
    gemm_kernel<1><<<dim3(16, 16), 256>>>(nullptr, wo, nullptr, nullptr,
                                          nullptr, nullptr, out);
}

// round 16
// speedup vs baseline: 1.0908x; 1.0018x over previous
#include <cuda_runtime.h>
#include <cstdint>
#include <cstddef>
#include <math_constants.h>

#define WIN_ 256
typedef unsigned long long u64;

// ---------------- packed f32x2 helpers ----------------
__device__ __forceinline__ u64 bc2(float x) {
    u64 r; asm("mov.b64 %0, {%1, %1};" : "=l"(r) : "f"(x)); return r;
}
__device__ __forceinline__ void fma2(u64& d, u64 a, u64 b) {
    asm("fma.rn.f32x2 %0, %1, %2, %0;" : "+l"(d) : "l"(a), "l"(b));
}
__device__ __forceinline__ void mul2(u64& d, u64 a) {
    asm("mul.rn.f32x2 %0, %0, %1;" : "+l"(d) : "l"(a));
}
__device__ __forceinline__ float2 up2(u64 v) {
    float2 f; asm("mov.b64 {%0, %1}, %2;" : "=f"(f.x), "=f"(f.y) : "l"(v)); return f;
}

// ---------------- device-global scratch ----------------
__device__ float g_q1[(size_t)2 * 16 * 1024 * 128];
__device__ float g_q2[(size_t)2 * 16 * 1024 * 128];
__device__ float g_k1[(size_t)2 * 8 * 1024 * 128];
__device__ float g_k2[(size_t)2 * 8 * 1024 * 128];
__device__ float g_v [(size_t)2 * 8 * 1024 * 128];
__device__ float g_ao[(size_t)2 * 1024 * 2048];
__device__ float g_probe[128];

// ============================================================================
// mma.sync probe: 1 warp, register-fed bf16 m16n8k16, no smem/ldmatrix.
// If HMMA faults on this harness, the whole bench fails -> decisive diagnosis.
// ============================================================================
__global__ void mma_probe_kernel()
{
    uint32_t a[4] = {0x3F803F80u, 0x3F803F80u, 0x3F803F80u, 0x3F803F80u};
    uint32_t bf[2] = {0x3F803F80u, 0x3F803F80u};
    float d[4] = {0.f, 0.f, 0.f, 0.f};
    asm volatile(
        "mma.sync.aligned.m16n8k16.row.col.f32.bf16.bf16.f32 "
        "{%0,%1,%2,%3}, {%4,%5,%6,%7}, {%8,%9}, {%0,%1,%2,%3};"
        : "+f"(d[0]), "+f"(d[1]), "+f"(d[2]), "+f"(d[3])
        : "r"(a[0]), "r"(a[1]), "r"(a[2]), "r"(a[3]), "r"(bf[0]), "r"(bf[1]));
    const int lane = threadIdx.x & 31;
    g_probe[lane * 4 + 0] = d[0];
    g_probe[lane * 4 + 1] = d[1];
    g_probe[lane * 4 + 2] = d[2];
    g_probe[lane * 4 + 3] = d[3];
}

// ============================================================================
// fp32 SGEMM 128x128 tile, BK=16, 256 threads, double-buffered, FFMA2 core.
// (Proven kernel, byte-identical — 699us control. LOCKED.)
// ============================================================================
template<int MODE>
__global__ __launch_bounds__(256, 2)
void gemm_kernel(const float* __restrict__ A,
                 const float* __restrict__ W0,
                 const float* __restrict__ W1,
                 const float* __restrict__ W2,
                 const float* __restrict__ fc,
                 const float* __restrict__ fs,
                 float* __restrict__ outp)
{
    __shared__ float As[2][16][132];
    __shared__ float Bs[2][16][128];

    const int tid = threadIdx.x;
    const int tx  = tid & 15;
    const int ty  = tid >> 4;
    const int bm  = blockIdx.y * 128;
    const int ct  = blockIdx.x;

    const float* Ap = (MODE == 1) ? g_ao : A;
    const float* Bp;
    int ldb, coff;
    if (MODE == 1)    { Bp = W0; ldb = 2048; coff = ct * 128; }
    else if (ct < 16) { Bp = W0; ldb = 2048; coff = ct * 128; }
    else if (ct < 24) { Bp = W1; ldb = 1024; coff = (ct - 16) * 128; }
    else              { Bp = W2; ldb = 1024; coff = (ct - 24) * 128; }

    const int K  = 2048;
    const int KT = K / 16;

    const int a_row = tid >> 2;
    const int a_k4  = (tid & 3) << 2;
    const int b_k   = tid >> 5;
    const int b_c4  = (tid & 31) << 2;

    u64 acc[8][4];
#pragma unroll
    for (int i = 0; i < 8; ++i)
#pragma unroll
        for (int j = 0; j < 4; ++j) acc[i][j] = 0ull;

    float4 ra[2], rb[2];
#pragma unroll
    for (int p = 0; p < 2; ++p) {
        ra[p] = *(const float4*)&Ap[(size_t)(bm + a_row + p * 64) * K + a_k4];
        rb[p] = *(const float4*)&Bp[(size_t)(b_k + p * 8) * ldb + coff + b_c4];
    }
#pragma unroll
    for (int p = 0; p < 2; ++p) {
        As[0][a_k4 + 0][a_row + p * 64] = ra[p].x;
        As[0][a_k4 + 1][a_row + p * 64] = ra[p].y;
        As[0][a_k4 + 2][a_row + p * 64] = ra[p].z;
        As[0][a_k4 + 3][a_row + p * 64] = ra[p].w;
        *(float4*)&Bs[0][b_k + p * 8][b_c4] = rb[p];
    }
    __syncthreads();

    for (int kt = 0; kt < KT; ++kt) {
        const int buf = kt & 1;
        if (kt + 1 < KT) {
            const int ko = (kt + 1) * 16;
#pragma unroll
            for (int p = 0; p < 2; ++p) {
                ra[p] = *(const float4*)&Ap[(size_t)(bm + a_row + p * 64) * K + ko + a_k4];
                rb[p] = *(const float4*)&Bp[(size_t)(ko + b_k + p * 8) * ldb + coff + b_c4];
            }
        }
#pragma unroll
        for (int k = 0; k < 16; ++k) {
            float4 a0 = *(const float4*)&As[buf][k][ty * 4];
            float4 a1 = *(const float4*)&As[buf][k][64 + ty * 4];
            ulonglong2 b0 = *(const ulonglong2*)&Bs[buf][k][tx * 4];
            ulonglong2 b1 = *(const ulonglong2*)&Bs[buf][k][64 + tx * 4];
            u64 bv[4] = {b0.x, b0.y, b1.x, b1.y};
            float av[8] = {a0.x, a0.y, a0.z, a0.w, a1.x, a1.y, a1.z, a1.w};
#pragma unroll
            for (int i = 0; i < 8; ++i) {
                u64 ai = bc2(av[i]);
#pragma unroll
                for (int j = 0; j < 4; ++j)
                    fma2(acc[i][j], ai, bv[j]);
            }
        }
        if (kt + 1 < KT) {
            const int nb = buf ^ 1;
#pragma unroll
            for (int p = 0; p < 2; ++p) {
                As[nb][a_k4 + 0][a_row + p * 64] = ra[p].x;
                As[nb][a_k4 + 1][a_row + p * 64] = ra[p].y;
                As[nb][a_k4 + 2][a_row + p * 64] = ra[p].z;
                As[nb][a_k4 + 3][a_row + p * 64] = ra[p].w;
                *(float4*)&Bs[nb][b_k + p * 8][b_c4] = rb[p];
            }
        }
        __syncthreads();
    }

    if (MODE == 0) {
#pragma unroll
        for (int i = 0; i < 8; ++i) {
            const int ml  = (i < 4) ? (ty * 4 + i) : (64 + ty * 4 + i - 4);
            const int row = bm + ml;
            const int bb  = row >> 10;
            const int ss  = row & 1023;
#pragma unroll
            for (int j2 = 0; j2 < 4; ++j2) {
                const int nl = (j2 < 2) ? (tx * 4 + 2 * j2) : (64 + tx * 4 + 2 * j2 - 4);
                const int t  = nl >> 1;
                float2 xz = up2(acc[i][j2]);
                const float xr = xz.x;
                const float xi = xz.y;
                if (ct < 16) {
                    const int h = ct;
                    const size_t off = ((size_t)(bb * 16 + h) * 1024 + ss) * 128 + nl;
                    const float c1 = fc[ss * 64 + t], s1 = fs[ss * 64 + t];
                    g_q1[off]     = xr * c1 - xi * s1;
                    g_q1[off + 1] = xr * s1 + xi * c1;
                    const float cw = fc[WIN_ * 64 + t], sw = fs[WIN_ * 64 + t];
                    g_q2[off]     = xr * cw - xi * sw;
                    g_q2[off + 1] = xr * sw + xi * cw;
                } else if (ct < 24) {
                    const int h = ct - 16;
                    const size_t off = ((size_t)(bb * 8 + h) * 1024 + ss) * 128 + nl;
                    const float c1 = fc[ss * 64 + t], s1 = fs[ss * 64 + t];
                    g_k1[off]     = xr * c1 - xi * s1;
                    g_k1[off + 1] = xr * s1 + xi * c1;
                    g_k2[off]     = xr;
                    g_k2[off + 1] = xi;
                } else {
                    const int h = ct - 24;
                    const size_t off = ((size_t)(bb * 8 + h) * 1024 + ss) * 128 + nl;
                    g_v[off]     = xr;
                    g_v[off + 1] = xi;
                }
            }
        }
    } else {
#pragma unroll
        for (int i = 0; i < 8; ++i) {
            const int ml = (i < 4) ? (ty * 4 + i) : (64 + ty * 4 + i - 4);
            const size_t row = (size_t)(bm + ml);
            float2 p0 = up2(acc[i][0]), p1 = up2(acc[i][1]);
            float2 p2 = up2(acc[i][2]), p3 = up2(acc[i][3]);
            *(float4*)&outp[row * 2048 + ct * 128 + tx * 4] =
                make_float4(p0.x, p0.y, p1.x, p1.y);
            *(float4*)&outp[row * 2048 + ct * 128 + 64 + tx * 4] =
                make_float4(p2.x, p2.y, p3.x, p3.y);
        }
    }
}

// ============================================================================
// Flash attention v7: R15 + PV V-load 1-ahead pipeline (FFMA order identical).
// ============================================================================
__device__ __forceinline__ void load_T64(float* __restrict__ dst,
                                         const float* __restrict__ src)
{
    const int t  = threadIdx.x;
    const int r  = t >> 2;
    const int d0 = (t & 3) * 32;
    const float* s = src + (size_t)r * 128 + d0;
#pragma unroll
    for (int q = 0; q < 8; ++q) {
        float4 v = *(const float4*)(s + q * 4);
        const int d = d0 + q * 4;
        dst[(d + 0) * 64 + r] = v.x;
        dst[(d + 1) * 64 + r] = v.y;
        dst[(d + 2) * 64 + r] = v.z;
        dst[(d + 3) * 64 + r] = v.w;
    }
}

// 2-stage software-pipelined QK (R15, proven).
__device__ __forceinline__ void qk_gemm(const float* __restrict__ Qs,
                                        const float* __restrict__ Ks,
                                        int ty, int tx, u64 Sp[4][2])
{
#pragma unroll
    for (int i = 0; i < 4; ++i) { Sp[i][0] = 0ull; Sp[i][1] = 0ull; }

    float4     ac = *(const float4*)&Qs[ty * 4];
    ulonglong2 bc = *(const ulonglong2*)&Ks[tx * 4];
#pragma unroll 4
    for (int d = 0; d < 128; ++d) {
        float4     an;
        ulonglong2 bn;
        if (d < 127) {
            an = *(const float4*)&Qs[(d + 1) * 64 + ty * 4];
            bn = *(const ulonglong2*)&Ks[(d + 1) * 64 + tx * 4];
        }
        float av[4] = {ac.x, ac.y, ac.z, ac.w};
#pragma unroll
        for (int i = 0; i < 4; ++i) {
            u64 ai = bc2(av[i]);
            fma2(Sp[i][0], ai, bc.x);
            fma2(Sp[i][1], ai, bc.y);
        }
        ac = an;
        bc = bn;
    }
}

__global__ __launch_bounds__(256, 1)
void flash_kernel()
{
    extern __shared__ float smf[];
    float* Qa  = smf;                 //  8192
    float* Qb  = smf + 8192;          //  8192
    float* Ksb = smf + 16384;         //  2 x 8192
    float* Vsb = smf + 32768;         //  2 x 8192
    float* Ps  = smf + 49152;         //  4096

    const int bh = blockIdx.y;
    const int b  = bh >> 4;
    const int h  = bh & 15;
    const int kh = h >> 1;
    const int qt = 15 - (int)blockIdx.x;
    const int i0 = qt * 64;

    const int tid = threadIdx.x;
    const int ty  = tid >> 4;
    const int tx  = tid & 15;
    const float scale = 0.08838834764831845f;

    const int lr  = tid >> 2;
    const int ld0 = (tid & 3) * 32;

    const float* kb1 = g_k1 + ((size_t)(b * 8 + kh) * 1024) * 128;
    const float* kb2 = g_k2 + ((size_t)(b * 8 + kh) * 1024) * 128;
    const float* vb  = g_v  + ((size_t)(b * 8 + kh) * 1024) * 128;

    float4 kreg[8], vreg[8];

#define ZONE_OF(j0) (((j0) >= i0 - 192) ? 0 : (((j0) == i0 - 256) ? 1 : 2))
#define PREFETCH(ktv) do { \
    const int j0p = (ktv) * 64; \
    const float* kb = ((ZONE_OF(j0p) == 2) ? kb2 : kb1) + (size_t)j0p * 128; \
    const float* vp = vb + (size_t)j0p * 128; \
    const float* ks = kb + (size_t)lr * 128 + ld0; \
    const float* vs = vp + (size_t)lr * 128 + ld0; \
    _Pragma("unroll") \
    for (int q = 0; q < 8; ++q) { \
        kreg[q] = *(const float4*)(ks + q * 4); \
        vreg[q] = *(const float4*)(vs + q * 4); \
    } } while (0)

    PREFETCH(0);
    load_T64(Qa, g_q1 + ((size_t)(b * 16 + h) * 1024 + i0) * 128);
    load_T64(Qb, g_q2 + ((size_t)(b * 16 + h) * 1024 + i0) * 128);

    u64 Op[4][4];
    float mo[4], l[4];
#pragma unroll
    for (int i = 0; i < 4; ++i) {
        mo[i] = -CUDART_INF_F;
        l[i]  = 0.f;
#pragma unroll
        for (int c = 0; c < 4; ++c) Op[i][c] = 0ull;
    }

    for (int kt = 0; kt <= qt; ++kt) {
        const int j0   = kt * 64;
        const int zone = ZONE_OF(j0);
        const int buf  = kt & 1;
        float* Ks = Ksb + buf * 8192;
        float* Vs = Vsb + buf * 8192;

#pragma unroll
        for (int q = 0; q < 8; ++q) {
            const int d = ld0 + q * 4;
            Ks[(d + 0) * 64 + lr] = kreg[q].x;
            Ks[(d + 1) * 64 + lr] = kreg[q].y;
            Ks[(d + 2) * 64 + lr] = kreg[q].z;
            Ks[(d + 3) * 64 + lr] = kreg[q].w;
            *(float4*)&Vs[lr * 128 + d] = vreg[q];
        }
        if (kt < qt) PREFETCH(kt + 1);
        __syncthreads();                 // the ONE block sync per tile

        u64 SpA[4][2];
        qk_gemm((zone == 2) ? Qb : Qa, Ks, ty, tx, SpA);

        float val[4][4];
        if (zone == 1) {
            float* Kalt = Ksb + (buf ^ 1) * 8192;
            __syncthreads();
            load_T64(Kalt, kb2 + (size_t)j0 * 128);
            __syncthreads();
            u64 SpB[4][2];
            qk_gemm(Qb, Kalt, ty, tx, SpB);
            __syncthreads();             // close race with kt+1's STS into buf^1
#pragma unroll
            for (int i = 0; i < 4; ++i) {
                const int ig = i0 + ty * 4 + i;
                float2 a0 = up2(SpA[i][0]), a1 = up2(SpA[i][1]);
                float2 b0 = up2(SpB[i][0]), b1 = up2(SpB[i][1]);
                float sa[4]  = {a0.x, a0.y, a1.x, a1.y};
                float sbv[4] = {b0.x, b0.y, b1.x, b1.y};
#pragma unroll
                for (int j = 0; j < 4; ++j) {
                    const int jg = j0 + tx * 4 + j;
                    val[i][j] = ((jg > ig - WIN_) ? sa[j] : sbv[j]) * scale;
                }
            }
        } else {
            const bool diag = (j0 == i0);
#pragma unroll
            for (int i = 0; i < 4; ++i) {
                const int ig = i0 + ty * 4 + i;
                float2 a0 = up2(SpA[i][0]), a1 = up2(SpA[i][1]);
                float sa[4] = {a0.x, a0.y, a1.x, a1.y};
#pragma unroll
                for (int j = 0; j < 4; ++j) {
                    const int jg = j0 + tx * 4 + j;
                    float v = sa[j] * scale;
                    if (diag && jg > ig) v = -CUDART_INF_F;
                    val[i][j] = v;
                }
            }
        }

        // --- online softmax (identical math) ---
        float mr[4], al[4];
#pragma unroll
        for (int i = 0; i < 4; ++i) {
            float m = val[i][0];
            m = fmaxf(m, val[i][1]);
            m = fmaxf(m, val[i][2]);
            m = fmaxf(m, val[i][3]);
#pragma unroll
            for (int off = 8; off >= 1; off >>= 1)
                m = fmaxf(m, __shfl_xor_sync(0xffffffffu, m, off));
            m = fmaxf(m, mo[i]);
            al[i] = __expf(mo[i] - m);
            mo[i] = m;
            float s = 0.f;
#pragma unroll
            for (int j = 0; j < 4; ++j) {
                float p = __expf(val[i][j] - m);
                val[i][j] = p;
                s += p;
            }
            mr[i] = s;
        }
#pragma unroll
        for (int i = 0; i < 4; ++i) {
            float s = mr[i];
#pragma unroll
            for (int off = 8; off >= 1; off >>= 1)
                s += __shfl_xor_sync(0xffffffffu, s, off);
            l[i] = l[i] * al[i] + s;
            u64 av = bc2(al[i]);
#pragma unroll
            for (int c = 0; c < 4; ++c) mul2(Op[i][c], av);
            *(float4*)&Ps[(ty * 4 + i) * 64 + tx * 4] =
                make_float4(val[i][0], val[i][1], val[i][2], val[i][3]);
        }
        __syncwarp();   // Ps producer == consumer warp

        // --- P @ V: Ps float4 blocks + V 1-ahead register pipeline ---
        ulonglong2 cv0 = *(const ulonglong2*)&Vs[tx * 4];
        ulonglong2 cv1 = *(const ulonglong2*)&Vs[64 + tx * 4];
#pragma unroll 2
        for (int j4 = 0; j4 < 64; j4 += 4) {
            float4 pr[4];
#pragma unroll
            for (int i = 0; i < 4; ++i)
                pr[i] = *(const float4*)&Ps[(ty * 4 + i) * 64 + j4];
            float pa[4][4] = {
                {pr[0].x, pr[0].y, pr[0].z, pr[0].w},
                {pr[1].x, pr[1].y, pr[1].z, pr[1].w},
                {pr[2].x, pr[2].y, pr[2].z, pr[2].w},
                {pr[3].x, pr[3].y, pr[3].z, pr[3].w}};
#pragma unroll
            for (int jj = 0; jj < 4; ++jj) {
                const int j = j4 + jj;
                ulonglong2 nv0, nv1;
                if (j < 63) {
                    nv0 = *(const ulonglong2*)&Vs[(j + 1) * 128 + tx * 4];
                    nv1 = *(const ulonglong2*)&Vs[(j + 1) * 128 + 64 + tx * 4];
                }
                u64 vv[4] = {cv0.x, cv0.y, cv1.x, cv1.y};
#pragma unroll
                for (int i = 0; i < 4; ++i) {
                    u64 pi = bc2(pa[i][jj]);
#pragma unroll
                    for (int c = 0; c < 4; ++c)
                        fma2(Op[i][c], pi, vv[c]);
                }
                cv0 = nv0;
                cv1 = nv1;
            }
        }
        // no tail sync (K/V double-buffered; WAR closed by the block sync)
    }

    // epilogue
#pragma unroll
    for (int i = 0; i < 4; ++i) {
        const float inv = 1.f / l[i];
        u64 iv = bc2(inv);
#pragma unroll
        for (int c = 0; c < 4; ++c) mul2(Op[i][c], iv);
        const int ig = i0 + ty * 4 + i;
        float* dst = g_ao + ((size_t)(b * 1024 + ig)) * 2048 + h * 128;
        float2 p0 = up2(Op[i][0]), p1 = up2(Op[i][1]);
        float2 p2 = up2(Op[i][2]), p3 = up2(Op[i][3]);
        *(float4*)&dst[tx * 4]      = make_float4(p0.x, p0.y, p1.x, p1.y);
        *(float4*)&dst[64 + tx * 4] = make_float4(p2.x, p2.y, p3.x, p3.y);
    }
#undef PREFETCH
#undef ZONE_OF
}

// ============================================================================
extern "C" void kernel_launch(void* const* d_in, const int* in_sizes, int n_in,
                              void* d_out, int out_size)
{
    const float* x  = (const float*)d_in[0];
    const float* fc = (const float*)d_in[1];
    const float* fs = (const float*)d_in[2];
    const float* wq = (const float*)d_in[3];
    const float* wk = (const float*)d_in[4];
    const float* wv = (const float*)d_in[5];
    const float* wo = (const float*)d_in[6];
    float* out = (float*)d_out;

    cudaFuncSetAttribute(flash_kernel,
                         cudaFuncAttributeMaxDynamicSharedMemorySize, 212992);

    mma_probe_kernel<<<1, 32>>>();   // 1-bit experiment: does HMMA execute?
    gemm_kernel<0><<<dim3(32, 16), 256>>>(x, wq, wk, wv, fc, fs, nullptr);
    flash_kernel<<<dim3(16, 32), 256, 212992>>>();
    gemm_kernel<1><<<dim3(16, 16), 256>>>(nullptr, wo, nullptr, nullptr,
                                          nullptr, nullptr, out);
}

// round 17
// speedup vs baseline: 1.1734x; 1.0757x over previous
#include <cuda_runtime.h>
#include <cuda_bf16.h>
#include <cstdint>
#include <cstddef>
#include <math_constants.h>

#define WIN_ 256
typedef unsigned long long u64;

// ---------------- packed f32x2 helpers ----------------
__device__ __forceinline__ u64 bc2(float x) {
    u64 r; asm("mov.b64 %0, {%1, %1};" : "=l"(r) : "f"(x)); return r;
}
__device__ __forceinline__ void fma2(u64& d, u64 a, u64 b) {
    asm("fma.rn.f32x2 %0, %1, %2, %0;" : "+l"(d) : "l"(a), "l"(b));
}
__device__ __forceinline__ void mul2(u64& d, u64 a) {
    asm("mul.rn.f32x2 %0, %0, %1;" : "+l"(d) : "l"(a));
}
__device__ __forceinline__ float2 up2(u64 v) {
    float2 f; asm("mov.b64 {%0, %1}, %2;" : "=f"(f.x), "=f"(f.y) : "l"(v)); return f;
}

// ---------------- device-global scratch ----------------
__device__ float g_q1[(size_t)2 * 16 * 1024 * 128];
__device__ float g_q2[(size_t)2 * 16 * 1024 * 128];
__device__ float g_k1[(size_t)2 * 8 * 1024 * 128];
__device__ float g_k2[(size_t)2 * 8 * 1024 * 128];
__device__ float g_v [(size_t)2 * 8 * 1024 * 128];
__device__ float g_ao[(size_t)2 * 1024 * 2048];

__device__ __align__(16) __nv_bfloat16 g_aoh [(size_t)2048 * 2048];
__device__ __align__(16) __nv_bfloat16 g_aol [(size_t)2048 * 2048];
__device__ __align__(16) __nv_bfloat16 g_bt1h[(size_t)2048 * 2048];  // woT [n][k]
__device__ __align__(16) __nv_bfloat16 g_bt1l[(size_t)2048 * 2048];

// ---------------- prep kernels ----------------
__device__ __forceinline__ void split1(float v, __nv_bfloat16& h, __nv_bfloat16& l) {
    h = __float2bfloat16(v);
    l = __float2bfloat16(v - __bfloat162float(h));
}

__global__ void split_ao_kernel() {
    size_t i = ((size_t)blockIdx.x * 256 + threadIdx.x) * 4;
    float4 v = *(const float4*)(g_ao + i);
    float a[4] = {v.x, v.y, v.z, v.w};
#pragma unroll
    for (int j = 0; j < 4; ++j) split1(a[j], g_aoh[i + j], g_aol[i + j]);
}

__global__ void tsplit_wo_kernel(const float* __restrict__ W) {
    __shared__ float smx[32][33];
    const int n0 = blockIdx.x * 32, k0 = blockIdx.y * 32;
    const int tx = threadIdx.x, ty = threadIdx.y;   // 32 x 8
#pragma unroll
    for (int i = 0; i < 4; ++i)
        smx[ty + i * 8][tx] = W[(size_t)(k0 + ty + i * 8) * 2048 + n0 + tx];
    __syncthreads();
#pragma unroll
    for (int i = 0; i < 4; ++i) {
        float v = smx[tx][ty + i * 8];
        size_t o = (size_t)(n0 + ty + i * 8) * 2048 + k0 + tx;
        split1(v, g_bt1h[o], g_bt1l[o]);
    }
}

// ============================================================================
// HMMA gemm<1>: out[2048,2048] = ao @ wo, bf16 hi/lo 3-pass via mma.sync.
// 128x128 CTA, BK=32, 8 warps (warp tile 64x32), static 40KB smem,
// plain-LDS fragments per documented m16n8k16 layout.
// ============================================================================
#define TSTRIDE 40
#define TELEMS  (128 * TSTRIDE)

__device__ __forceinline__ void mma_bf16(float d[4], const uint32_t a[4],
                                         const uint32_t b[2]) {
    asm volatile(
        "mma.sync.aligned.m16n8k16.row.col.f32.bf16.bf16.f32 "
        "{%0,%1,%2,%3}, {%4,%5,%6,%7}, {%8,%9}, {%0,%1,%2,%3};"
        : "+f"(d[0]), "+f"(d[1]), "+f"(d[2]), "+f"(d[3])
        : "r"(a[0]), "r"(a[1]), "r"(a[2]), "r"(a[3]), "r"(b[0]), "r"(b[1]));
}

__global__ __launch_bounds__(256)
void hmma_gemm1(float* __restrict__ outp)
{
    __shared__ __nv_bfloat16 smt[4 * TELEMS];   // Ah, Al, Bh, Bl

    const int tid  = threadIdx.x;
    const int wid  = tid >> 5;
    const int lane = tid & 31;
    const int wm   = wid & 1;
    const int wn   = wid >> 1;
    const int m0   = blockIdx.y * 128;
    const int ct   = blockIdx.x;

    const __nv_bfloat16* pAh = g_aoh  + (size_t)m0 * 2048;
    const __nv_bfloat16* pAl = g_aol  + (size_t)m0 * 2048;
    const __nv_bfloat16* pBh = g_bt1h + (size_t)ct * 128 * 2048;
    const __nv_bfloat16* pBl = g_bt1l + (size_t)ct * 128 * 2048;

    const int lr = tid >> 2;          // 0..63 (+64 second row)
    const int lc = (tid & 3) * 8;     // bf16 col in BK=32

    float acc[4][4][4];
#pragma unroll
    for (int f = 0; f < 4; ++f)
#pragma unroll
        for (int g = 0; g < 4; ++g)
#pragma unroll
            for (int c = 0; c < 4; ++c) acc[f][g][c] = 0.f;

    uint4 rg[8];
#define LOAD_REGS(kcv) do { \
    const size_t ko = (size_t)(kcv) * 32 + lc; \
    rg[0] = *(const uint4*)(pAh + (size_t)lr * 2048 + ko); \
    rg[1] = *(const uint4*)(pAh + (size_t)(lr + 64) * 2048 + ko); \
    rg[2] = *(const uint4*)(pAl + (size_t)lr * 2048 + ko); \
    rg[3] = *(const uint4*)(pAl + (size_t)(lr + 64) * 2048 + ko); \
    rg[4] = *(const uint4*)(pBh + (size_t)lr * 2048 + ko); \
    rg[5] = *(const uint4*)(pBh + (size_t)(lr + 64) * 2048 + ko); \
    rg[6] = *(const uint4*)(pBl + (size_t)lr * 2048 + ko); \
    rg[7] = *(const uint4*)(pBl + (size_t)(lr + 64) * 2048 + ko); \
} while (0)
#define STORE_REGS() do { \
    *(uint4*)(smt + lr * TSTRIDE + lc)                         = rg[0]; \
    *(uint4*)(smt + (lr + 64) * TSTRIDE + lc)                  = rg[1]; \
    *(uint4*)(smt + TELEMS + lr * TSTRIDE + lc)                = rg[2]; \
    *(uint4*)(smt + TELEMS + (lr + 64) * TSTRIDE + lc)         = rg[3]; \
    *(uint4*)(smt + 2 * TELEMS + lr * TSTRIDE + lc)            = rg[4]; \
    *(uint4*)(smt + 2 * TELEMS + (lr + 64) * TSTRIDE + lc)     = rg[5]; \
    *(uint4*)(smt + 3 * TELEMS + lr * TSTRIDE + lc)            = rg[6]; \
    *(uint4*)(smt + 3 * TELEMS + (lr + 64) * TSTRIDE + lc)     = rg[7]; \
} while (0)

    const int g4 = lane >> 2;
    const int t4 = (lane & 3) * 2;

    LOAD_REGS(0);

    for (int kc = 0; kc < 64; ++kc) {
        if (kc) __syncthreads();
        STORE_REGS();
        __syncthreads();
        if (kc + 1 < 64) LOAD_REGS(kc + 1);

#pragma unroll
        for (int ks = 0; ks < 2; ++ks) {
            const int kk = ks * 16 + t4;
            uint32_t ahf[4][4], alf[4][4];
#pragma unroll
            for (int f = 0; f < 4; ++f) {
                const int r = wm * 64 + f * 16 + g4;
                const __nv_bfloat16* A0 = smt;
                const __nv_bfloat16* A1 = smt + TELEMS;
                ahf[f][0] = *(const uint32_t*)(A0 + r * TSTRIDE + kk);
                ahf[f][1] = *(const uint32_t*)(A0 + (r + 8) * TSTRIDE + kk);
                ahf[f][2] = *(const uint32_t*)(A0 + r * TSTRIDE + kk + 8);
                ahf[f][3] = *(const uint32_t*)(A0 + (r + 8) * TSTRIDE + kk + 8);
                alf[f][0] = *(const uint32_t*)(A1 + r * TSTRIDE + kk);
                alf[f][1] = *(const uint32_t*)(A1 + (r + 8) * TSTRIDE + kk);
                alf[f][2] = *(const uint32_t*)(A1 + r * TSTRIDE + kk + 8);
                alf[f][3] = *(const uint32_t*)(A1 + (r + 8) * TSTRIDE + kk + 8);
            }
#pragma unroll
            for (int g = 0; g < 4; ++g) {
                const int n = wn * 32 + g * 8 + g4;
                const __nv_bfloat16* B0 = smt + 2 * TELEMS;
                const __nv_bfloat16* B1 = smt + 3 * TELEMS;
                uint32_t bh[2], bl[2];
                bh[0] = *(const uint32_t*)(B0 + n * TSTRIDE + kk);
                bh[1] = *(const uint32_t*)(B0 + n * TSTRIDE + kk + 8);
                bl[0] = *(const uint32_t*)(B1 + n * TSTRIDE + kk);
                bl[1] = *(const uint32_t*)(B1 + n * TSTRIDE + kk + 8);
#pragma unroll
                for (int f = 0; f < 4; ++f) {
                    mma_bf16(acc[f][g], ahf[f], bh);
                    mma_bf16(acc[f][g], ahf[f], bl);
                    mma_bf16(acc[f][g], alf[f], bh);
                }
            }
        }
    }

    // epilogue: c0,c1 -> (row g, cols 2t,2t+1); c2,c3 -> (row g+8)
#pragma unroll
    for (int f = 0; f < 4; ++f)
#pragma unroll
        for (int half = 0; half < 2; ++half) {
            const int row = m0 + wm * 64 + f * 16 + g4 + half * 8;
#pragma unroll
            for (int g = 0; g < 4; ++g) {
                const int col = ct * 128 + wn * 32 + g * 8 + t4;
                *(float2*)(outp + (size_t)row * 2048 + col) =
                    make_float2(acc[f][g][half * 2], acc[f][g][half * 2 + 1]);
            }
        }
#undef LOAD_REGS
#undef STORE_REGS
}

// ============================================================================
// fp32 SGEMM 128x128 (proven, LOCKED) — used for MODE 0 (QKV+RoPE) only.
// ============================================================================
template<int MODE>
__global__ __launch_bounds__(256, 2)
void gemm_kernel(const float* __restrict__ A,
                 const float* __restrict__ W0,
                 const float* __restrict__ W1,
                 const float* __restrict__ W2,
                 const float* __restrict__ fc,
                 const float* __restrict__ fs,
                 float* __restrict__ outp)
{
    __shared__ float As[2][16][132];
    __shared__ float Bs[2][16][128];

    const int tid = threadIdx.x;
    const int tx  = tid & 15;
    const int ty  = tid >> 4;
    const int bm  = blockIdx.y * 128;
    const int ct  = blockIdx.x;

    const float* Ap = (MODE == 1) ? g_ao : A;
    const float* Bp;
    int ldb, coff;
    if (MODE == 1)    { Bp = W0; ldb = 2048; coff = ct * 128; }
    else if (ct < 16) { Bp = W0; ldb = 2048; coff = ct * 128; }
    else if (ct < 24) { Bp = W1; ldb = 1024; coff = (ct - 16) * 128; }
    else              { Bp = W2; ldb = 1024; coff = (ct - 24) * 128; }

    const int K  = 2048;
    const int KT = K / 16;

    const int a_row = tid >> 2;
    const int a_k4  = (tid & 3) << 2;
    const int b_k   = tid >> 5;
    const int b_c4  = (tid & 31) << 2;

    u64 acc[8][4];
#pragma unroll
    for (int i = 0; i < 8; ++i)
#pragma unroll
        for (int j = 0; j < 4; ++j) acc[i][j] = 0ull;

    float4 ra[2], rb[2];
#pragma unroll
    for (int p = 0; p < 2; ++p) {
        ra[p] = *(const float4*)&Ap[(size_t)(bm + a_row + p * 64) * K + a_k4];
        rb[p] = *(const float4*)&Bp[(size_t)(b_k + p * 8) * ldb + coff + b_c4];
    }
#pragma unroll
    for (int p = 0; p < 2; ++p) {
        As[0][a_k4 + 0][a_row + p * 64] = ra[p].x;
        As[0][a_k4 + 1][a_row + p * 64] = ra[p].y;
        As[0][a_k4 + 2][a_row + p * 64] = ra[p].z;
        As[0][a_k4 + 3][a_row + p * 64] = ra[p].w;
        *(float4*)&Bs[0][b_k + p * 8][b_c4] = rb[p];
    }
    __syncthreads();

    for (int kt = 0; kt < KT; ++kt) {
        const int buf = kt & 1;
        if (kt + 1 < KT) {
            const int ko = (kt + 1) * 16;
#pragma unroll
            for (int p = 0; p < 2; ++p) {
                ra[p] = *(const float4*)&Ap[(size_t)(bm + a_row + p * 64) * K + ko + a_k4];
                rb[p] = *(const float4*)&Bp[(size_t)(ko + b_k + p * 8) * ldb + coff + b_c4];
            }
        }
#pragma unroll
        for (int k = 0; k < 16; ++k) {
            float4 a0 = *(const float4*)&As[buf][k][ty * 4];
            float4 a1 = *(const float4*)&As[buf][k][64 + ty * 4];
            ulonglong2 b0 = *(const ulonglong2*)&Bs[buf][k][tx * 4];
            ulonglong2 b1 = *(const ulonglong2*)&Bs[buf][k][64 + tx * 4];
            u64 bv[4] = {b0.x, b0.y, b1.x, b1.y};
            float av[8] = {a0.x, a0.y, a0.z, a0.w, a1.x, a1.y, a1.z, a1.w};
#pragma unroll
            for (int i = 0; i < 8; ++i) {
                u64 ai = bc2(av[i]);
#pragma unroll
                for (int j = 0; j < 4; ++j)
                    fma2(acc[i][j], ai, bv[j]);
            }
        }
        if (kt + 1 < KT) {
            const int nb = buf ^ 1;
#pragma unroll
            for (int p = 0; p < 2; ++p) {
                As[nb][a_k4 + 0][a_row + p * 64] = ra[p].x;
                As[nb][a_k4 + 1][a_row + p * 64] = ra[p].y;
                As[nb][a_k4 + 2][a_row + p * 64] = ra[p].z;
                As[nb][a_k4 + 3][a_row + p * 64] = ra[p].w;
                *(float4*)&Bs[nb][b_k + p * 8][b_c4] = rb[p];
            }
        }
        __syncthreads();
    }

    if (MODE == 0) {
#pragma unroll
        for (int i = 0; i < 8; ++i) {
            const int ml  = (i < 4) ? (ty * 4 + i) : (64 + ty * 4 + i - 4);
            const int row = bm + ml;
            const int bb  = row >> 10;
            const int ss  = row & 1023;
#pragma unroll
            for (int j2 = 0; j2 < 4; ++j2) {
                const int nl = (j2 < 2) ? (tx * 4 + 2 * j2) : (64 + tx * 4 + 2 * j2 - 4);
                const int t  = nl >> 1;
                float2 xz = up2(acc[i][j2]);
                const float xr = xz.x;
                const float xi = xz.y;
                if (ct < 16) {
                    const int h = ct;
                    const size_t off = ((size_t)(bb * 16 + h) * 1024 + ss) * 128 + nl;
                    const float c1 = fc[ss * 64 + t], s1 = fs[ss * 64 + t];
                    g_q1[off]     = xr * c1 - xi * s1;
                    g_q1[off + 1] = xr * s1 + xi * c1;
                    const float cw = fc[WIN_ * 64 + t], sw = fs[WIN_ * 64 + t];
                    g_q2[off]     = xr * cw - xi * sw;
                    g_q2[off + 1] = xr * sw + xi * cw;
                } else if (ct < 24) {
                    const int h = ct - 16;
                    const size_t off = ((size_t)(bb * 8 + h) * 1024 + ss) * 128 + nl;
                    const float c1 = fc[ss * 64 + t], s1 = fs[ss * 64 + t];
                    g_k1[off]     = xr * c1 - xi * s1;
                    g_k1[off + 1] = xr * s1 + xi * c1;
                    g_k2[off]     = xr;
                    g_k2[off + 1] = xi;
                } else {
                    const int h = ct - 24;
                    const size_t off = ((size_t)(bb * 8 + h) * 1024 + ss) * 128 + nl;
                    g_v[off]     = xr;
                    g_v[off + 1] = xi;
                }
            }
        }
    } else {
#pragma unroll
        for (int i = 0; i < 8; ++i) {
            const int ml = (i < 4) ? (ty * 4 + i) : (64 + ty * 4 + i - 4);
            const size_t row = (size_t)(bm + ml);
            float2 p0 = up2(acc[i][0]), p1 = up2(acc[i][1]);
            float2 p2 = up2(acc[i][2]), p3 = up2(acc[i][3]);
            *(float4*)&outp[row * 2048 + ct * 128 + tx * 4] =
                make_float4(p0.x, p0.y, p1.x, p1.y);
            *(float4*)&outp[row * 2048 + ct * 128 + 64 + tx * 4] =
                make_float4(p2.x, p2.y, p3.x, p3.y);
        }
    }
}

// ============================================================================
// Flash attention v7 — byte-identical to R16 best.
// ============================================================================
__device__ __forceinline__ void load_T64(float* __restrict__ dst,
                                         const float* __restrict__ src)
{
    const int t  = threadIdx.x;
    const int r  = t >> 2;
    const int d0 = (t & 3) * 32;
    const float* s = src + (size_t)r * 128 + d0;
#pragma unroll
    for (int q = 0; q < 8; ++q) {
        float4 v = *(const float4*)(s + q * 4);
        const int d = d0 + q * 4;
        dst[(d + 0) * 64 + r] = v.x;
        dst[(d + 1) * 64 + r] = v.y;
        dst[(d + 2) * 64 + r] = v.z;
        dst[(d + 3) * 64 + r] = v.w;
    }
}

__device__ __forceinline__ void qk_gemm(const float* __restrict__ Qs,
                                        const float* __restrict__ Ks,
                                        int ty, int tx, u64 Sp[4][2])
{
#pragma unroll
    for (int i = 0; i < 4; ++i) { Sp[i][0] = 0ull; Sp[i][1] = 0ull; }

    float4     ac = *(const float4*)&Qs[ty * 4];
    ulonglong2 bc = *(const ulonglong2*)&Ks[tx * 4];
#pragma unroll 4
    for (int d = 0; d < 128; ++d) {
        float4     an;
        ulonglong2 bn;
        if (d < 127) {
            an = *(const float4*)&Qs[(d + 1) * 64 + ty * 4];
            bn = *(const ulonglong2*)&Ks[(d + 1) * 64 + tx * 4];
        }
        float av[4] = {ac.x, ac.y, ac.z, ac.w};
#pragma unroll
        for (int i = 0; i < 4; ++i) {
            u64 ai = bc2(av[i]);
            fma2(Sp[i][0], ai, bc.x);
            fma2(Sp[i][1], ai, bc.y);
        }
        ac = an;
        bc = bn;
    }
}

__global__ __launch_bounds__(256, 1)
void flash_kernel()
{
    extern __shared__ float smf[];
    float* Qa  = smf;
    float* Qb  = smf + 8192;
    float* Ksb = smf + 16384;
    float* Vsb = smf + 32768;
    float* Ps  = smf + 49152;

    const int bh = blockIdx.y;
    const int b  = bh >> 4;
    const int h  = bh & 15;
    const int kh = h >> 1;
    const int qt = 15 - (int)blockIdx.x;
    const int i0 = qt * 64;

    const int tid = threadIdx.x;
    const int ty  = tid >> 4;
    const int tx  = tid & 15;
    const float scale = 0.08838834764831845f;

    const int lr  = tid >> 2;
    const int ld0 = (tid & 3) * 32;

    const float* kb1 = g_k1 + ((size_t)(b * 8 + kh) * 1024) * 128;
    const float* kb2 = g_k2 + ((size_t)(b * 8 + kh) * 1024) * 128;
    const float* vb  = g_v  + ((size_t)(b * 8 + kh) * 1024) * 128;

    float4 kreg[8], vreg[8];

#define ZONE_OF(j0) (((j0) >= i0 - 192) ? 0 : (((j0) == i0 - 256) ? 1 : 2))
#define PREFETCH(ktv) do { \
    const int j0p = (ktv) * 64; \
    const float* kb = ((ZONE_OF(j0p) == 2) ? kb2 : kb1) + (size_t)j0p * 128; \
    const float* vp = vb + (size_t)j0p * 128; \
    const float* ks = kb + (size_t)lr * 128 + ld0; \
    const float* vs = vp + (size_t)lr * 128 + ld0; \
    _Pragma("unroll") \
    for (int q = 0; q < 8; ++q) { \
        kreg[q] = *(const float4*)(ks + q * 4); \
        vreg[q] = *(const float4*)(vs + q * 4); \
    } } while (0)

    PREFETCH(0);
    load_T64(Qa, g_q1 + ((size_t)(b * 16 + h) * 1024 + i0) * 128);
    load_T64(Qb, g_q2 + ((size_t)(b * 16 + h) * 1024 + i0) * 128);

    u64 Op[4][4];
    float mo[4], l[4];
#pragma unroll
    for (int i = 0; i < 4; ++i) {
        mo[i] = -CUDART_INF_F;
        l[i]  = 0.f;
#pragma unroll
        for (int c = 0; c < 4; ++c) Op[i][c] = 0ull;
    }

    for (int kt = 0; kt <= qt; ++kt) {
        const int j0   = kt * 64;
        const int zone = ZONE_OF(j0);
        const int buf  = kt & 1;
        float* Ks = Ksb + buf * 8192;
        float* Vs = Vsb + buf * 8192;

#pragma unroll
        for (int q = 0; q < 8; ++q) {
            const int d = ld0 + q * 4;
            Ks[(d + 0) * 64 + lr] = kreg[q].x;
            Ks[(d + 1) * 64 + lr] = kreg[q].y;
            Ks[(d + 2) * 64 + lr] = kreg[q].z;
            Ks[(d + 3) * 64 + lr] = kreg[q].w;
            *(float4*)&Vs[lr * 128 + d] = vreg[q];
        }
        if (kt < qt) PREFETCH(kt + 1);
        __syncthreads();

        u64 SpA[4][2];
        qk_gemm((zone == 2) ? Qb : Qa, Ks, ty, tx, SpA);

        float val[4][4];
        if (zone == 1) {
            float* Kalt = Ksb + (buf ^ 1) * 8192;
            __syncthreads();
            load_T64(Kalt, kb2 + (size_t)j0 * 128);
            __syncthreads();
            u64 SpB[4][2];
            qk_gemm(Qb, Kalt, ty, tx, SpB);
            __syncthreads();
#pragma unroll
            for (int i = 0; i < 4; ++i) {
                const int ig = i0 + ty * 4 + i;
                float2 a0 = up2(SpA[i][0]), a1 = up2(SpA[i][1]);
                float2 b0 = up2(SpB[i][0]), b1 = up2(SpB[i][1]);
                float sa[4]  = {a0.x, a0.y, a1.x, a1.y};
                float sbv[4] = {b0.x, b0.y, b1.x, b1.y};
#pragma unroll
                for (int j = 0; j < 4; ++j) {
                    const int jg = j0 + tx * 4 + j;
                    val[i][j] = ((jg > ig - WIN_) ? sa[j] : sbv[j]) * scale;
                }
            }
        } else {
            const bool diag = (j0 == i0);
#pragma unroll
            for (int i = 0; i < 4; ++i) {
                const int ig = i0 + ty * 4 + i;
                float2 a0 = up2(SpA[i][0]), a1 = up2(SpA[i][1]);
                float sa[4] = {a0.x, a0.y, a1.x, a1.y};
#pragma unroll
                for (int j = 0; j < 4; ++j) {
                    const int jg = j0 + tx * 4 + j;
                    float v = sa[j] * scale;
                    if (diag && jg > ig) v = -CUDART_INF_F;
                    val[i][j] = v;
                }
            }
        }

        float mr[4], al[4];
#pragma unroll
        for (int i = 0; i < 4; ++i) {
            float m = val[i][0];
            m = fmaxf(m, val[i][1]);
            m = fmaxf(m, val[i][2]);
            m = fmaxf(m, val[i][3]);
#pragma unroll
            for (int off = 8; off >= 1; off >>= 1)
                m = fmaxf(m, __shfl_xor_sync(0xffffffffu, m, off));
            m = fmaxf(m, mo[i]);
            al[i] = __expf(mo[i] - m);
            mo[i] = m;
            float s = 0.f;
#pragma unroll
            for (int j = 0; j < 4; ++j) {
                float p = __expf(val[i][j] - m);
                val[i][j] = p;
                s += p;
            }
            mr[i] = s;
        }
#pragma unroll
        for (int i = 0; i < 4; ++i) {
            float s = mr[i];
#pragma unroll
            for (int off = 8; off >= 1; off >>= 1)
                s += __shfl_xor_sync(0xffffffffu, s, off);
            l[i] = l[i] * al[i] + s;
            u64 av = bc2(al[i]);
#pragma unroll
            for (int c = 0; c < 4; ++c) mul2(Op[i][c], av);
            *(float4*)&Ps[(ty * 4 + i) * 64 + tx * 4] =
                make_float4(val[i][0], val[i][1], val[i][2], val[i][3]);
        }
        __syncwarp();

        ulonglong2 cv0 = *(const ulonglong2*)&Vs[tx * 4];
        ulonglong2 cv1 = *(const ulonglong2*)&Vs[64 + tx * 4];
#pragma unroll 2
        for (int j4 = 0; j4 < 64; j4 += 4) {
            float4 pr[4];
#pragma unroll
            for (int i = 0; i < 4; ++i)
                pr[i] = *(const float4*)&Ps[(ty * 4 + i) * 64 + j4];
            float pa[4][4] = {
                {pr[0].x, pr[0].y, pr[0].z, pr[0].w},
                {pr[1].x, pr[1].y, pr[1].z, pr[1].w},
                {pr[2].x, pr[2].y, pr[2].z, pr[2].w},
                {pr[3].x, pr[3].y, pr[3].z, pr[3].w}};
#pragma unroll
            for (int jj = 0; jj < 4; ++jj) {
                const int j = j4 + jj;
                ulonglong2 nv0, nv1;
                if (j < 63) {
                    nv0 = *(const ulonglong2*)&Vs[(j + 1) * 128 + tx * 4];
                    nv1 = *(const ulonglong2*)&Vs[(j + 1) * 128 + 64 + tx * 4];
                }
                u64 vv[4] = {cv0.x, cv0.y, cv1.x, cv1.y};
#pragma unroll
                for (int i = 0; i < 4; ++i) {
                    u64 pi = bc2(pa[i][jj]);
#pragma unroll
                    for (int c = 0; c < 4; ++c)
                        fma2(Op[i][c], pi, vv[c]);
                }
                cv0 = nv0;
                cv1 = nv1;
            }
        }
    }

#pragma unroll
    for (int i = 0; i < 4; ++i) {
        const float inv = 1.f / l[i];
        u64 iv = bc2(inv);
#pragma unroll
        for (int c = 0; c < 4; ++c) mul2(Op[i][c], iv);
        const int ig = i0 + ty * 4 + i;
        float* dst = g_ao + ((size_t)(b * 1024 + ig)) * 2048 + h * 128;
        float2 p0 = up2(Op[i][0]), p1 = up2(Op[i][1]);
        float2 p2 = up2(Op[i][2]), p3 = up2(Op[i][3]);
        *(float4*)&dst[tx * 4]      = make_float4(p0.x, p0.y, p1.x, p1.y);
        *(float4*)&dst[64 + tx * 4] = make_float4(p2.x, p2.y, p3.x, p3.y);
    }
#undef PREFETCH
#undef ZONE_OF
}

// ============================================================================
extern "C" void kernel_launch(void* const* d_in, const int* in_sizes, int n_in,
                              void* d_out, int out_size)
{
    const float* x  = (const float*)d_in[0];
    const float* fc = (const float*)d_in[1];
    const float* fs = (const float*)d_in[2];
    const float* wq = (const float*)d_in[3];
    const float* wk = (const float*)d_in[4];
    const float* wv = (const float*)d_in[5];
    const float* wo = (const float*)d_in[6];
    float* out = (float*)d_out;

    cudaFuncSetAttribute(flash_kernel,
                         cudaFuncAttributeMaxDynamicSharedMemorySize, 212992);

    tsplit_wo_kernel<<<dim3(64, 64), dim3(32, 8)>>>(wo);   // independent of x
    gemm_kernel<0><<<dim3(32, 16), 256>>>(x, wq, wk, wv, fc, fs, nullptr);
    flash_kernel<<<dim3(16, 32), 256, 212992>>>();
    split_ao_kernel<<<4096, 256>>>();
    hmma_gemm1<<<dim3(16, 16), 256>>>(out);
}